// round 9
// baseline (speedup 1.0000x reference)
#include <cuda_runtime.h>
#include <cstdint>

#define L_SEQ   1024
#define KNN     48
#define H       128
#define N_EDGES (L_SEQ * KNN)       // 49152
#define TILE_E  128
#define N_TILES (N_EDGES / TILE_E)  // 384
#define GRID_MAIN 148
#define NTHREADS 512

__device__ float d_hv[L_SEQ * H];   // LN+W1 output (512 KB scratch)

// smem layout (bytes): two P buffers (hi 32K + lo 32K each), W2-lo, b2
#define SM_P0    0
#define SM_P1    65536
#define SM_W2LO  131072
#define SM_B2    163840
#define SM_TOTAL (163840 + 512 + 128)   // 164480 B  (1 CTA/SM)
#define P_LO_OFF 32768                  // lo half within a P buffer

// ---------------------------------------------------------------------------
__device__ __forceinline__ uint32_t smem_to_u32(const void* p) {
    uint32_t a;
    asm("{ .reg .u64 t; cvta.to.shared.u64 t, %1; cvt.u32.u64 %0, t; }"
        : "=r"(a) : "l"(p));
    return a;
}

// XOR swizzle on 16B chunks within a 256B row (conflict-free ldmatrix/STS)
__device__ __forceinline__ uint32_t swz(uint32_t row, uint32_t chunk) {
    return (chunk & 8u) | ((chunk ^ row) & 7u);
}

// split (a,b) fp32 pair into packed bf16x2 hi + bf16x2 lo (a -> low 16 bits)
__device__ __forceinline__ void split2(float a, float b, uint32_t& hi, uint32_t& lo) {
    uint32_t h;
    asm("cvt.rn.bf16x2.f32 %0, %1, %2;" : "=r"(h) : "f"(b), "f"(a));
    float ha = __uint_as_float(h << 16);
    float hb = __uint_as_float(h & 0xFFFF0000u);
    float la = a - ha;
    float lb = b - hb;
    asm("cvt.rn.bf16x2.f32 %0, %1, %2;" : "=r"(lo) : "f"(lb), "f"(la));
    hi = h;
}

__device__ __forceinline__ void ldsm_x4(uint32_t* r, uint32_t addr) {
    asm volatile("ldmatrix.sync.aligned.m8n8.x4.shared.b16 {%0,%1,%2,%3}, [%4];"
                 : "=r"(r[0]), "=r"(r[1]), "=r"(r[2]), "=r"(r[3]) : "r"(addr));
}

__device__ __forceinline__ void mma_bf16(float* c, const uint32_t* a,
                                         uint32_t b0, uint32_t b1) {
    asm("mma.sync.aligned.m16n8k16.row.col.f32.bf16.bf16.f32 "
        "{%0,%1,%2,%3}, {%4,%5,%6,%7}, {%8,%9}, {%0,%1,%2,%3};"
        : "+f"(c[0]), "+f"(c[1]), "+f"(c[2]), "+f"(c[3])
        : "r"(a[0]), "r"(a[1]), "r"(a[2]), "r"(a[3]), "r"(b0), "r"(b1));
}

// ---------------------------------------------------------------------------
// Kernel 1: LayerNorm + Linear1 -> d_hv.  8 rows/block, 128 threads, 128 blocks.
// ---------------------------------------------------------------------------
__global__ void __launch_bounds__(128) ln_w1_kernel(
    const float* __restrict__ hV, const float* __restrict__ W1,
    const float* __restrict__ b1, const float* __restrict__ ln_scale,
    const float* __restrict__ ln_bias) {
    __shared__ float xs[8][H];
    int t = threadIdx.x, w = t >> 5, lane = t & 31;
    int i0 = blockIdx.x * 8;

    float4 g = reinterpret_cast<const float4*>(ln_scale)[lane];
    float4 c = reinterpret_cast<const float4*>(ln_bias)[lane];

    #pragma unroll
    for (int rr = 0; rr < 2; rr++) {
        int r = w + rr * 4;
        float4 x = reinterpret_cast<const float4*>(hV + (size_t)(i0 + r) * H)[lane];
        float s = x.x + x.y + x.z + x.w;
        #pragma unroll
        for (int off = 16; off; off >>= 1) s += __shfl_xor_sync(~0u, s, off);
        float mu = s * (1.0f / H);
        float4 d = make_float4(x.x - mu, x.y - mu, x.z - mu, x.w - mu);
        float sq = d.x * d.x + d.y * d.y + d.z * d.z + d.w * d.w;
        #pragma unroll
        for (int off = 16; off; off >>= 1) sq += __shfl_xor_sync(~0u, sq, off);
        float rs = rsqrtf(sq * (1.0f / H) + 1e-5f);
        float4 o = make_float4(d.x * rs * g.x + c.x, d.y * rs * g.y + c.y,
                               d.z * rs * g.z + c.z, d.w * rs * g.w + c.w);
        reinterpret_cast<float4*>(xs[r])[lane] = o;
    }
    __syncthreads();

    float acc[8];
    float bt = b1[t];
    #pragma unroll
    for (int r = 0; r < 8; r++) acc[r] = bt;
    const float4* wrow = reinterpret_cast<const float4*>(W1 + (size_t)t * H);
    #pragma unroll 4
    for (int q = 0; q < H / 4; q++) {
        float4 w4 = wrow[q];
        #pragma unroll
        for (int r = 0; r < 8; r++) {
            float4 x4 = reinterpret_cast<const float4*>(xs[r])[q];
            acc[r] += w4.x * x4.x + w4.y * x4.y + w4.z * x4.z + w4.w * x4.w;
        }
    }
    #pragma unroll
    for (int r = 0; r < 8; r++) d_hv[(size_t)(i0 + r) * H + t] = acc[r];
}

// ---------------------------------------------------------------------------
// build P tile (hi/lo bf16, swizzled [edge][h]) into given buffer
// 512 threads, 128 edges -> 4 threads/edge, each covers 32 h values
// ---------------------------------------------------------------------------
__device__ __forceinline__ void build_p(char* smemc, uint32_t bufoff, int tile,
                                        const int* __restrict__ Eidx, int t) {
    int m  = t >> 2;             // edge row in tile (0..127)
    int q4 = t & 3;              // h quarter (32 values)
    int e = tile * TILE_E + m;
    int i = (int)((unsigned)e / KNN);
    int j = __ldg(Eidx + e);
    const float4* pi = reinterpret_cast<const float4*>(d_hv + (size_t)i * H + q4 * 32);
    const float4* pj = reinterpret_cast<const float4*>(d_hv + (size_t)j * H + q4 * 32);
    uint32_t rowbase = (uint32_t)m * 256;
    #pragma unroll
    for (int q = 0; q < 4; q++) {          // 4 chunks of 8 h values
        float4 x0 = pi[2 * q], x1 = pi[2 * q + 1];
        float4 y0 = pj[2 * q], y1 = pj[2 * q + 1];
        uint4 hi4, lo4;
        split2(x0.x * y0.x, x0.y * y0.y, hi4.x, lo4.x);
        split2(x0.z * y0.z, x0.w * y0.w, hi4.y, lo4.y);
        split2(x1.x * y1.x, x1.y * y1.y, hi4.z, lo4.z);
        split2(x1.z * y1.z, x1.w * y1.w, hi4.w, lo4.w);
        uint32_t off = rowbase + swz((uint32_t)m, (uint32_t)(q4 * 4 + q)) * 16;
        *reinterpret_cast<uint4*>(smemc + bufoff + off) = hi4;
        *reinterpret_cast<uint4*>(smemc + bufoff + P_LO_OFF + off) = lo4;
    }
}

// ---------------------------------------------------------------------------
// Kernel 2: C[49152,128] = P @ W2^T, A-stationary (W2-hi in registers),
// double-buffered P so gather overlaps mma.  512 thr = 8(m16) x 2(n64) warps.
// ---------------------------------------------------------------------------
__global__ void __launch_bounds__(NTHREADS, 1) outer_w2_mma_kernel(
    const int* __restrict__ Eidx, const float* __restrict__ W2,
    const float* __restrict__ b2, float* __restrict__ out) {
    extern __shared__ char smemc[];
    const uint32_t sb = smem_to_u32(smemc);
    int t = threadIdx.x;
    int warp = t >> 5, lane = t & 31;
    int wm = warp >> 1;     // 0..7  m16 output tile
    int wn = warp & 1;      // 0..1  n64 edge half

    // ---- stage W2: hi into P0 (temp), lo into persistent SM_W2LO; b2 ----
    for (int g = t; g < 2048; g += NTHREADS) {
        int o = g >> 4;                // output feature row
        int ch = g & 15;               // 16B chunk within row
        const float4* w = reinterpret_cast<const float4*>(W2 + (size_t)o * H + ch * 8);
        float4 w0 = w[0], w1 = w[1];
        uint4 hi4, lo4;
        split2(w0.x, w0.y, hi4.x, lo4.x);
        split2(w0.z, w0.w, hi4.y, lo4.y);
        split2(w1.x, w1.y, hi4.z, lo4.z);
        split2(w1.z, w1.w, hi4.w, lo4.w);
        uint32_t off = (uint32_t)o * 256 + swz(o, ch) * 16;
        *reinterpret_cast<uint4*>(smemc + SM_P0 + off) = hi4;
        *reinterpret_cast<uint4*>(smemc + SM_W2LO + off) = lo4;
    }
    if (t < 128) reinterpret_cast<float*>(smemc + SM_B2)[t] = b2[t];
    __syncthreads();

    // ---- preload A-hi fragments (W2-hi rows wm*16..wm*16+15, all k) ----
    const uint32_t m_a   = (uint32_t)(wm * 16 + (lane & 15));
    const uint32_t a_sel = (uint32_t)(lane >> 4);
    uint32_t ah[8][4];
    #pragma unroll
    for (int f = 0; f < 8; f++) {
        uint32_t chunkA = (uint32_t)(2 * f) + a_sel;
        ldsm_x4(ah[f], sb + SM_P0 + m_a * 256 + swz(m_a, chunkA) * 16);
    }
    const uint32_t alo_row = sb + SM_W2LO + m_a * 256;
    __syncthreads();   // W2-hi in P0 is dead after this point

    // B-side (P) ldmatrix address components
    const uint32_t b_row7   = (uint32_t)(lane & 7);
    const uint32_t b_rowoff = b_row7 * 256;
    const uint32_t b_sel    = (uint32_t)(lane >> 3);

    // per-thread epilogue constants
    const int o0 = wm * 16 + (lane >> 2);
    const float b2a = reinterpret_cast<const float*>(smemc + SM_B2)[o0];
    const float b2b = reinterpret_cast<const float*>(smemc + SM_B2)[o0 + 8];

    // ---- pipelined tile loop ----
    int tile = blockIdx.x;
    if (tile < N_TILES) build_p(smemc, SM_P0, tile, Eidx, t);
    __syncthreads();

    uint32_t bufoff = SM_P0;
    for (; tile < N_TILES; tile += gridDim.x) {
        int nxt = tile + (int)gridDim.x;
        if (nxt < N_TILES) build_p(smemc, bufoff ^ SM_P1, nxt, Eidx, t);

        // ---- mma: m16 x n64 for this warp, K=128, 3-term bf16 split ----
        float acc[8][4];
        #pragma unroll
        for (int nt = 0; nt < 8; nt++)
            #pragma unroll
            for (int q = 0; q < 4; q++) acc[nt][q] = 0.0f;

        #pragma unroll
        for (int kp = 0; kp < 4; kp++) {        // k32 steps
            // A-lo frags for this k32 (from persistent W2LO)
            uint32_t al0[4], al1[4];
            ldsm_x4(al0, alo_row + swz(m_a, (uint32_t)(4 * kp) + a_sel) * 16);
            ldsm_x4(al1, alo_row + swz(m_a, (uint32_t)(4 * kp + 2) + a_sel) * 16);

            uint32_t chunkB = (uint32_t)(kp * 4) + b_sel;
            uint32_t bcol = swz(b_row7, chunkB) * 16;
            #pragma unroll
            for (int nt = 0; nt < 8; nt++) {
                uint32_t e8 = (uint32_t)(wn * 8 + nt);
                uint32_t baddr = sb + bufoff + e8 * 2048 + b_rowoff + bcol;
                uint32_t bh[4], bl[4];
                ldsm_x4(bh, baddr);
                ldsm_x4(bl, baddr + P_LO_OFF);
                mma_bf16(acc[nt], ah[2 * kp],     bh[0], bh[1]);  // hi*hi (k lo)
                mma_bf16(acc[nt], ah[2 * kp],     bl[0], bl[1]);  // hi*lo
                mma_bf16(acc[nt], al0,            bh[0], bh[1]);  // lo*hi
                mma_bf16(acc[nt], ah[2 * kp + 1], bh[2], bh[3]);  // hi*hi (k hi)
                mma_bf16(acc[nt], ah[2 * kp + 1], bl[2], bl[3]);  // hi*lo
                mma_bf16(acc[nt], al1,            bh[2], bh[3]);  // lo*hi
            }
        }

        // ---- epilogue: C[m=o, n=e] -> out[e][o] + b2 ----
        {
            int e_base = tile * TILE_E + wn * 64 + (lane & 3) * 2;
            #pragma unroll
            for (int nt = 0; nt < 8; nt++) {
                int e = e_base + nt * 8;
                float* p0 = out + (size_t)e * H;
                p0[o0]           = acc[nt][0] + b2a;
                p0[H + o0]       = acc[nt][1] + b2a;
                p0[o0 + 8]       = acc[nt][2] + b2b;
                p0[H + o0 + 8]   = acc[nt][3] + b2b;
            }
        }
        __syncthreads();       // build[next] done; reads of buf done
        bufoff ^= SM_P1;
    }
}

// ---------------------------------------------------------------------------
extern "C" void kernel_launch(void* const* d_in, const int* in_sizes, int n_in,
                              void* d_out, int out_size) {
    const float* hV       = (const float*)d_in[0];
    const int*   Eidx     = (const int*)d_in[1];
    const float* W1       = (const float*)d_in[2];
    const float* b1       = (const float*)d_in[3];
    const float* W2       = (const float*)d_in[4];
    const float* b2       = (const float*)d_in[5];
    const float* ln_scale = (const float*)d_in[6];
    const float* ln_bias  = (const float*)d_in[7];
    float* out = (float*)d_out;

    cudaFuncSetAttribute(outer_w2_mma_kernel,
                         cudaFuncAttributeMaxDynamicSharedMemorySize, SM_TOTAL);

    ln_w1_kernel<<<L_SEQ / 8, 128>>>(hV, W1, b1, ln_scale, ln_bias);
    outer_w2_mma_kernel<<<GRID_MAIN, NTHREADS, SM_TOTAL>>>(Eidx, W2, b2, out);
}